// round 7
// baseline (speedup 1.0000x reference)
#include <cuda_runtime.h>
#include <math.h>
#include <stdint.h>

#define HQ   32
#define HKV  8
#define DH   128
#define HID  4096
#define IM   12288
#define SEQ  8192
#define EPSR 1e-6f
#define NSPL 16           // KV splits per head for flash decoding

// ---------------- scratch (device globals; no allocation allowed) ----------
__device__ __align__(16) float g_qkv[HQ*DH + 2*HKV*DH];  // q | k | v raw projections
__device__ __align__(16) float g_knew[HKV*DH];           // new K row (post rope)
__device__ __align__(16) float g_vnew[HKV*DH];           // new V row
__device__ __align__(16) float g_attn[HQ*DH];            // attention output
__device__ __align__(16) float g_h1[HID];                // residual + o_proj
__device__ __align__(16) float g_m[IM];                  // silu(gate)*up
// split-KV partials + completion counters
__device__ __align__(16) float g_pacc[HQ*NSPL*DH];
__device__ float g_pm[HQ*NSPL];
__device__ float g_pl[HQ*NSPL];
__device__ int   g_cnt[HQ];                              // zero-init; self-resetting

// ---------------- helpers --------------------------------------------------
__device__ __forceinline__ float warp_sum(float v) {
    #pragma unroll
    for (int o = 16; o; o >>= 1) v += __shfl_xor_sync(0xffffffffu, v, o);
    return v;
}

// ============ fused RMSNorm + QKV GEMV (2 rows/warp) =======================
// block = 256 (8 warps) -> 16 rows/block.
__global__ void gemv_qkv_k(const float* __restrict__ x, const float* __restrict__ lnw,
                           const float* __restrict__ Wq, const float* __restrict__ Wk,
                           const float* __restrict__ Wv) {
    __shared__ float4 sx[HID/4];
    __shared__ float red[8];
    int tid = threadIdx.x, warp = tid >> 5, lane = tid & 31;
    const float4* x4 = reinterpret_cast<const float4*>(x);
    const float4* w4 = reinterpret_cast<const float4*>(lnw);
    float ssq = 0.f;
    #pragma unroll
    for (int i = tid; i < HID/4; i += 256) {
        float4 v = __ldg(x4 + i);
        float4 w = __ldg(w4 + i);
        ssq += v.x*v.x + v.y*v.y + v.z*v.z + v.w*v.w;
        sx[i] = make_float4(v.x*w.x, v.y*w.y, v.z*w.z, v.w*w.w);
    }
    ssq = warp_sum(ssq);
    if (lane == 0) red[warp] = ssq;
    __syncthreads();

    int r0 = blockIdx.x * 16 + warp * 2;
    int r1 = r0 + 1;
    auto rowp = [&](int r) -> const float4* {
        const float* row;
        if (r < HQ*DH)                  row = Wq + (size_t)r * HID;
        else if (r < HQ*DH + HKV*DH)    row = Wk + (size_t)(r - HQ*DH) * HID;
        else                            row = Wv + (size_t)(r - HQ*DH - HKV*DH) * HID;
        return reinterpret_cast<const float4*>(row);
    };
    const float4* wr0 = rowp(r0);
    const float4* wr1 = rowp(r1);
    float s0 = 0.f, s1 = 0.f;
    #pragma unroll 8
    for (int i = lane; i < HID/4; i += 32) {
        float4 b = sx[i];
        float4 a0 = __ldcs(wr0 + i);
        float4 a1 = __ldcs(wr1 + i);
        s0 += a0.x*b.x + a0.y*b.y + a0.z*b.z + a0.w*b.w;
        s1 += a1.x*b.x + a1.y*b.y + a1.z*b.z + a1.w*b.w;
    }
    s0 = warp_sum(s0);
    s1 = warp_sum(s1);
    if (lane == 0) {
        float tot = red[0]+red[1]+red[2]+red[3]+red[4]+red[5]+red[6]+red[7];
        float inv = rsqrtf(tot / (float)HID + EPSR);
        g_qkv[r0] = s0 * inv;
        g_qkv[r1] = s1 * inv;
    }
}

// ============ attention: fused rope + split-KV partials + last-block merge =
__global__ void attn_k(const float* __restrict__ posp,
                       const float* __restrict__ Kc, const float* __restrict__ Vc,
                       const float* __restrict__ cosv, const float* __restrict__ sinv,
                       const float* __restrict__ qw, const float* __restrict__ kw) {
    const float scale = 0.088388347648318447f;  // 128^-0.5
    int qh = blockIdx.x / NSPL;
    int sp = blockIdx.x % NSPL;
    int kv = qh >> 2;
    int tid = threadIdx.x;
    int warp = tid >> 5, lane = tid & 31;

    __shared__ __align__(16) float sq[DH], sk[DH], sv[DH];
    __shared__ float redq[4], redk[4];

    // ---- prologue: per-head RMSNorm + RoPE (threads 0-127: q, 128-255: k/v)
    int t = tid & 127;
    bool doq = tid < 128;
    float v = doq ? g_qkv[qh*DH + t] : g_qkv[HQ*DH + kv*DH + t];
    float ss = warp_sum(v * v);
    if (lane == 0) { if (doq) redq[warp] = ss; else redk[warp - 4] = ss; }
    if (!doq) sv[t] = g_qkv[HQ*DH + HKV*DH + kv*DH + t];
    __syncthreads();
    float tot = doq ? (redq[0]+redq[1]+redq[2]+redq[3])
                    : (redk[0]+redk[1]+redk[2]+redk[3]);
    float inv = rsqrtf(tot / (float)DH + EPSR);
    float nv = v * inv * (doq ? qw[t] : kw[t]);
    if (doq) sq[t] = nv; else sk[t] = nv;
    __syncthreads();
    float partner;
    if (doq) partner = (t < DH/2) ? -sq[t + DH/2] : sq[t - DH/2];
    else     partner = (t < DH/2) ? -sk[t + DH/2] : sk[t - DH/2];
    float roped = nv * cosv[t] + partner * sinv[t];
    __syncthreads();
    if (doq) sq[t] = roped; else sk[t] = roped;
    __syncthreads();
    if (sp == 0 && (qh & 3) == 0 && !doq) {
        g_knew[kv*DH + t] = roped;
        g_vnew[kv*DH + t] = sv[t];
    }

    // ---- split-KV mainloop (batched 4 keys per warp iteration)
    int p = (int)posp[0];
    int total = p + 1;
    int chunk = (total + NSPL - 1) / NSPL;
    int beg = sp * chunk;
    int end = min(beg + chunk, total);
    const float* K = Kc + (size_t)kv * SEQ * DH;
    const float* V = Vc + (size_t)kv * SEQ * DH;
    float4 q = reinterpret_cast<const float4*>(sq)[lane];

    float m = -INFINITY, l = 0.f;
    float4 acc = make_float4(0.f, 0.f, 0.f, 0.f);
    for (int base = beg; base < end; base += 32) {
        float4 kx[4], vx[4];
        bool val[4];
        #pragma unroll
        for (int tt = 0; tt < 4; tt++) {
            int j = base + warp + 8*tt;
            val[tt] = (j < end);
            int jj = val[tt] ? j : beg;
            if (jj == p) {
                kx[tt] = reinterpret_cast<const float4*>(sk)[lane];
                vx[tt] = reinterpret_cast<const float4*>(sv)[lane];
            } else {
                kx[tt] = __ldg(reinterpret_cast<const float4*>(K + (size_t)jj * DH) + lane);
                vx[tt] = __ldg(reinterpret_cast<const float4*>(V + (size_t)jj * DH) + lane);
            }
        }
        float d[4];
        #pragma unroll
        for (int tt = 0; tt < 4; tt++)
            d[tt] = q.x*kx[tt].x + q.y*kx[tt].y + q.z*kx[tt].z + q.w*kx[tt].w;
        #pragma unroll
        for (int o = 16; o; o >>= 1) {
            #pragma unroll
            for (int tt = 0; tt < 4; tt++) d[tt] += __shfl_xor_sync(0xffffffffu, d[tt], o);
        }
        #pragma unroll
        for (int tt = 0; tt < 4; tt++) d[tt] = val[tt] ? d[tt] * scale : -INFINITY;
        float mb = fmaxf(fmaxf(d[0], d[1]), fmaxf(d[2], d[3]));
        if (mb > -INFINITY) {
            float mn = fmaxf(m, mb);
            float corr = (m > -INFINITY) ? __expf(m - mn) : 0.f;
            l *= corr;
            acc.x *= corr; acc.y *= corr; acc.z *= corr; acc.w *= corr;
            #pragma unroll
            for (int tt = 0; tt < 4; tt++) {
                if (val[tt]) {
                    float w = __expf(d[tt] - mn);
                    l += w;
                    acc.x += w * vx[tt].x; acc.y += w * vx[tt].y;
                    acc.z += w * vx[tt].z; acc.w += w * vx[tt].w;
                }
            }
            m = mn;
        }
    }

    // ---- block-level merge of 8 warps -> one partial
    __shared__ float s_m[8], s_l[8];
    __shared__ float s_acc[8][DH];
    if (lane == 0) { s_m[warp] = m; s_l[warp] = l; }
    s_acc[warp][4*lane + 0] = acc.x;
    s_acc[warp][4*lane + 1] = acc.y;
    s_acc[warp][4*lane + 2] = acc.z;
    s_acc[warp][4*lane + 3] = acc.w;
    __syncthreads();
    if (tid < DH) {
        int d = tid;
        float M = -INFINITY;
        #pragma unroll
        for (int w = 0; w < 8; w++) M = fmaxf(M, s_m[w]);
        float L = 0.f, A = 0.f;
        #pragma unroll
        for (int w = 0; w < 8; w++) {
            float f = (s_m[w] > -INFINITY) ? __expf(s_m[w] - M) : 0.f;
            L += s_l[w] * f;
            A += s_acc[w][d] * f;
        }
        g_pacc[(size_t)blockIdx.x * DH + d] = A;
        if (d == 0) { g_pm[blockIdx.x] = M; g_pl[blockIdx.x] = L; }
    }

    // ---- last block for this head merges all splits
    __shared__ int s_merge;
    __threadfence();
    __syncthreads();
    if (tid == 0) {
        int old = atomicAdd(&g_cnt[qh], 1);
        s_merge = (old == NSPL - 1);
        if (s_merge) g_cnt[qh] = 0;      // reset for next graph replay
    }
    __syncthreads();
    if (s_merge) {
        __threadfence();
        if (tid < DH) {
            int d = tid;
            float M = -INFINITY;
            #pragma unroll
            for (int s = 0; s < NSPL; s++) M = fmaxf(M, g_pm[qh*NSPL + s]);
            float L = 0.f, A = 0.f;
            #pragma unroll
            for (int s = 0; s < NSPL; s++) {
                float pm = g_pm[qh*NSPL + s];
                float f = (pm > -INFINITY) ? __expf(pm - M) : 0.f;
                L += g_pl[qh*NSPL + s] * f;
                A += g_pacc[(size_t)(qh*NSPL + s) * DH + d] * f;
            }
            g_attn[qh*DH + d] = A / L;
        }
    }
}

// ---------------- O projection + residual (2 rows/warp) ---------------------
__global__ void gemv_o_k(const float* __restrict__ Wo, const float* __restrict__ resid) {
    __shared__ float4 sx[(HQ*DH)/4];
    int tid = threadIdx.x, warp = tid >> 5, lane = tid & 31;
    const float4* a4 = reinterpret_cast<const float4*>(g_attn);
    #pragma unroll
    for (int i = tid; i < (HQ*DH)/4; i += 256) sx[i] = a4[i];
    __syncthreads();
    int r0 = blockIdx.x * 16 + warp * 2;
    int r1 = r0 + 1;
    const float4* w0 = reinterpret_cast<const float4*>(Wo + (size_t)r0 * (HQ*DH));
    const float4* w1 = reinterpret_cast<const float4*>(Wo + (size_t)r1 * (HQ*DH));
    float s0 = 0.f, s1 = 0.f;
    #pragma unroll 8
    for (int i = lane; i < (HQ*DH)/4; i += 32) {
        float4 b = sx[i];
        float4 a0 = __ldcs(w0 + i);
        float4 a1 = __ldcs(w1 + i);
        s0 += a0.x*b.x + a0.y*b.y + a0.z*b.z + a0.w*b.w;
        s1 += a1.x*b.x + a1.y*b.y + a1.z*b.z + a1.w*b.w;
    }
    s0 = warp_sum(s0);
    s1 = warp_sum(s1);
    if (lane == 0) {
        g_h1[r0] = resid[r0] + s0;
        g_h1[r1] = resid[r1] + s1;
    }
}

// ============ fused RMSNorm + gate/up GEMV (2 rows/warp, 4 streams) ========
__global__ void gemv_gateup_k(const float* __restrict__ lnw,
                              const float* __restrict__ Wg, const float* __restrict__ Wu) {
    __shared__ float4 sx[HID/4];
    __shared__ float red[8];
    int tid = threadIdx.x, warp = tid >> 5, lane = tid & 31;
    const float4* x4 = reinterpret_cast<const float4*>(g_h1);
    const float4* w4 = reinterpret_cast<const float4*>(lnw);
    float ssq = 0.f;
    #pragma unroll
    for (int i = tid; i < HID/4; i += 256) {
        float4 v = x4[i];
        float4 w = __ldg(w4 + i);
        ssq += v.x*v.x + v.y*v.y + v.z*v.z + v.w*v.w;
        sx[i] = make_float4(v.x*w.x, v.y*w.y, v.z*w.z, v.w*w.w);
    }
    ssq = warp_sum(ssq);
    if (lane == 0) red[warp] = ssq;
    __syncthreads();

    int r0 = blockIdx.x * 16 + warp * 2;
    int r1 = r0 + 1;
    const float4* g0 = reinterpret_cast<const float4*>(Wg + (size_t)r0 * HID);
    const float4* g1 = reinterpret_cast<const float4*>(Wg + (size_t)r1 * HID);
    const float4* u0 = reinterpret_cast<const float4*>(Wu + (size_t)r0 * HID);
    const float4* u1 = reinterpret_cast<const float4*>(Wu + (size_t)r1 * HID);
    float sg0 = 0.f, su0 = 0.f, sg1 = 0.f, su1 = 0.f;
    #pragma unroll 4
    for (int i = lane; i < HID/4; i += 32) {
        float4 b = sx[i];
        float4 a0 = __ldcs(g0 + i);
        float4 a1 = __ldcs(g1 + i);
        float4 c0 = __ldcs(u0 + i);
        float4 c1 = __ldcs(u1 + i);
        sg0 += a0.x*b.x + a0.y*b.y + a0.z*b.z + a0.w*b.w;
        sg1 += a1.x*b.x + a1.y*b.y + a1.z*b.z + a1.w*b.w;
        su0 += c0.x*b.x + c0.y*b.y + c0.z*b.z + c0.w*b.w;
        su1 += c1.x*b.x + c1.y*b.y + c1.z*b.z + c1.w*b.w;
    }
    sg0 = warp_sum(sg0);
    sg1 = warp_sum(sg1);
    su0 = warp_sum(su0);
    su1 = warp_sum(su1);
    if (lane == 0) {
        float tot = red[0]+red[1]+red[2]+red[3]+red[4]+red[5]+red[6]+red[7];
        float inv = rsqrtf(tot / (float)HID + EPSR);
        sg0 *= inv; su0 *= inv; sg1 *= inv; su1 *= inv;
        g_m[r0] = (sg0 / (1.f + __expf(-sg0))) * su0;
        g_m[r1] = (sg1 / (1.f + __expf(-sg1))) * su1;
    }
}

// ---------------- down GEMV + residual (2 rows/warp, 48KB smem) ------------
__global__ void gemv_down_k(const float* __restrict__ Wd, float* __restrict__ out) {
    __shared__ float4 sx[IM/4];          // 48 KB
    int tid = threadIdx.x, warp = tid >> 5, lane = tid & 31;
    const float4* m4 = reinterpret_cast<const float4*>(g_m);
    #pragma unroll
    for (int i = tid; i < IM/4; i += 256) sx[i] = m4[i];
    __syncthreads();
    int r0 = blockIdx.x * 16 + warp * 2;
    int r1 = r0 + 1;
    const float4* w0 = reinterpret_cast<const float4*>(Wd + (size_t)r0 * IM);
    const float4* w1 = reinterpret_cast<const float4*>(Wd + (size_t)r1 * IM);
    float s0 = 0.f, s1 = 0.f;
    #pragma unroll 8
    for (int i = lane; i < IM/4; i += 32) {
        float4 b = sx[i];
        float4 a0 = __ldcs(w0 + i);
        float4 a1 = __ldcs(w1 + i);
        s0 += a0.x*b.x + a0.y*b.y + a0.z*b.z + a0.w*b.w;
        s1 += a1.x*b.x + a1.y*b.y + a1.z*b.z + a1.w*b.w;
    }
    s0 = warp_sum(s0);
    s1 = warp_sum(s1);
    if (lane == 0) {
        out[r0] = g_h1[r0] + s0;
        out[r1] = g_h1[r1] + s1;
    }
}

// ---------------- patch row `pos` of the copied caches ---------------------
__global__ void patch_k(const float* __restrict__ posp,
                        float* __restrict__ out_k, float* __restrict__ out_v) {
    int i = threadIdx.x;                 // 0..1023 = HKV*DH
    int head = i >> 7, t = i & 127;
    int p = (int)posp[0];
    size_t off = (size_t)head * SEQ * DH + (size_t)p * DH + t;
    out_k[off] = g_knew[i];
    out_v[off] = g_vnew[i];
}

// ---------------- launch ----------------------------------------------------
extern "C" void kernel_launch(void* const* d_in, const int* in_sizes, int n_in,
                              void* d_out, int out_size) {
    const float* x      = (const float*)d_in[0];
    const float* pos    = (const float*)d_in[1];
    const float* cosv   = (const float*)d_in[2];
    const float* sinv   = (const float*)d_in[3];
    const float* kcache = (const float*)d_in[4];
    const float* vcache = (const float*)d_in[5];
    const float* Wq     = (const float*)d_in[6];
    const float* Wk     = (const float*)d_in[7];
    const float* Wv     = (const float*)d_in[8];
    const float* Wo     = (const float*)d_in[9];
    const float* Wg     = (const float*)d_in[10];
    const float* Wu     = (const float*)d_in[11];
    const float* Wd     = (const float*)d_in[12];
    const float* qnw    = (const float*)d_in[13];
    const float* knw    = (const float*)d_in[14];
    const float* ln1w   = (const float*)d_in[15];
    const float* ln2w   = (const float*)d_in[16];

    float* out   = (float*)d_out;
    float* out_k = out + HID;
    float* out_v = out_k + (size_t)HKV * SEQ * DH;
    const size_t cache_bytes = (size_t)HKV * SEQ * DH * sizeof(float);

    static cudaStream_t s2 = nullptr;
    static cudaEvent_t ev_fork = nullptr, ev_join = nullptr;
    if (!s2) {
        cudaStreamCreateWithFlags(&s2, cudaStreamNonBlocking);
        cudaEventCreateWithFlags(&ev_fork, cudaEventDisableTiming);
        cudaEventCreateWithFlags(&ev_join, cudaEventDisableTiming);
    }

    // Fork: bulk cache copy runs concurrently with the whole compute pipeline.
    cudaEventRecord(ev_fork, 0);
    cudaStreamWaitEvent(s2, ev_fork, 0);
    cudaMemcpyAsync(out_k, kcache, cache_bytes, cudaMemcpyDeviceToDevice, s2);
    cudaMemcpyAsync(out_v, vcache, cache_bytes, cudaMemcpyDeviceToDevice, s2);
    cudaEventRecord(ev_join, s2);

    gemv_qkv_k<<<(HQ*DH + 2*HKV*DH) / 16, 256>>>(x, ln1w, Wq, Wk, Wv);
    attn_k<<<HQ * NSPL, 256>>>(pos, kcache, vcache, cosv, sinv, qnw, knw);
    gemv_o_k<<<HID / 16, 256>>>(Wo, x);
    gemv_gateup_k<<<IM / 16, 256>>>(ln2w, Wg, Wu);
    gemv_down_k<<<HID / 16, 256>>>(Wd, out);

    // Join: patch the freshly written row into the copied caches.
    cudaStreamWaitEvent(0, ev_join, 0);
    patch_k<<<1, HKV * DH>>>(pos, out_k, out_v);
}

// round 9
// speedup vs baseline: 1.0179x; 1.0179x over previous
#include <cuda_runtime.h>
#include <math.h>
#include <stdint.h>

#define HQ   32
#define HKV  8
#define DH   128
#define HID  4096
#define IM   12288
#define SEQ  8192
#define EPSR 1e-6f
#define NSPL 16           // KV splits per head for flash decoding

// ---------------- scratch (device globals; no allocation allowed) ----------
__device__ __align__(16) float g_qkv[HQ*DH + 2*HKV*DH];  // q | k | v raw projections
__device__ __align__(16) float g_knew[HKV*DH];           // new K row (post rope)
__device__ __align__(16) float g_vnew[HKV*DH];           // new V row
__device__ __align__(16) float g_attn[HQ*DH];            // attention output
__device__ __align__(16) float g_h1[HID];                // residual + o_proj
__device__ __align__(16) float g_m[IM];                  // silu(gate)*up
// split-KV partials + completion counters
__device__ __align__(16) float g_pacc[HQ*NSPL*DH];
__device__ float g_pm[HQ*NSPL];
__device__ float g_pl[HQ*NSPL];
__device__ int   g_cnt[HQ];                              // zero-init; self-resetting

// ---------------- helpers --------------------------------------------------
__device__ __forceinline__ float warp_sum(float v) {
    #pragma unroll
    for (int o = 16; o; o >>= 1) v += __shfl_xor_sync(0xffffffffu, v, o);
    return v;
}
__device__ __forceinline__ void l2_prefetch(const void* p) {
    asm volatile("prefetch.global.L2 [%0];" :: "l"(p));
}

// ============ fused RMSNorm + QKV GEMV (1 row/warp) ========================
__global__ void gemv_qkv_k(const float* __restrict__ x, const float* __restrict__ lnw,
                           const float* __restrict__ Wq, const float* __restrict__ Wk,
                           const float* __restrict__ Wv) {
    cudaTriggerProgrammaticLaunchCompletion();
    __shared__ float4 sx[HID/4];
    __shared__ float red[8];
    int tid = threadIdx.x, warp = tid >> 5, lane = tid & 31;

    int r = blockIdx.x * 8 + warp;
    const float* row;
    if (r < HQ*DH)                  row = Wq + (size_t)r * HID;
    else if (r < HQ*DH + HKV*DH)    row = Wk + (size_t)(r - HQ*DH) * HID;
    else                            row = Wv + (size_t)(r - HQ*DH - HKV*DH) * HID;
    // prefetch own weight row (16 KB) into L2 — independent of everything
    #pragma unroll
    for (int off = lane * 128; off < HID * 4; off += 32 * 128)
        l2_prefetch((const char*)row + off);
    cudaGridDependencySynchronize();

    const float4* x4 = reinterpret_cast<const float4*>(x);
    const float4* w4 = reinterpret_cast<const float4*>(lnw);
    float ssq = 0.f;
    #pragma unroll
    for (int i = tid; i < HID/4; i += 256) {
        float4 v = __ldg(x4 + i);
        float4 w = __ldg(w4 + i);
        ssq += v.x*v.x + v.y*v.y + v.z*v.z + v.w*v.w;
        sx[i] = make_float4(v.x*w.x, v.y*w.y, v.z*w.z, v.w*w.w);
    }
    ssq = warp_sum(ssq);
    if (lane == 0) red[warp] = ssq;
    __syncthreads();

    const float4* wr = reinterpret_cast<const float4*>(row);
    float s = 0.f;
    #pragma unroll 8
    for (int i = lane; i < HID/4; i += 32) {
        float4 a = __ldcs(wr + i); float4 b = sx[i];
        s += a.x*b.x + a.y*b.y + a.z*b.z + a.w*b.w;
    }
    s = warp_sum(s);
    if (lane == 0) {
        float tot = red[0]+red[1]+red[2]+red[3]+red[4]+red[5]+red[6]+red[7];
        g_qkv[r] = s * rsqrtf(tot / (float)HID + EPSR);
    }
}

// ============ attention: fused rope + split-KV partials + last-block merge =
__global__ void attn_k(const float* __restrict__ posp,
                       const float* __restrict__ Kc, const float* __restrict__ Vc,
                       const float* __restrict__ cosv, const float* __restrict__ sinv,
                       const float* __restrict__ qw, const float* __restrict__ kw) {
    cudaTriggerProgrammaticLaunchCompletion();
    const float scale = 0.088388347648318447f;  // 128^-0.5
    int qh = blockIdx.x / NSPL;
    int sp = blockIdx.x % NSPL;
    int kv = qh >> 2;
    int tid = threadIdx.x;
    int warp = tid >> 5, lane = tid & 31;

    // posp / K / V are harness inputs — independent of gemv_qkv. Prefetch our
    // K/V chunk into L2 while the QKV GEMV drains.
    int p = (int)__ldg(posp);
    int total = p + 1;
    int chunk = (total + NSPL - 1) / NSPL;
    int beg = sp * chunk;
    int end = min(beg + chunk, total);
    const float* K = Kc + (size_t)kv * SEQ * DH;
    const float* V = Vc + (size_t)kv * SEQ * DH;
    {
        int nlines = (end - beg) * 4;              // 512 B/row = 4 lines
        for (int i = tid; i < nlines; i += 256) {
            int r = beg + (i >> 2);
            int off = (i & 3) * 128;
            l2_prefetch((const char*)(K + (size_t)r * DH) + off);
            l2_prefetch((const char*)(V + (size_t)r * DH) + off);
        }
    }
    cudaGridDependencySynchronize();

    __shared__ __align__(16) float sq[DH], sk[DH], sv[DH];
    __shared__ float redq[4], redk[4];

    // ---- prologue: per-head RMSNorm + RoPE (threads 0-127: q, 128-255: k/v)
    int t = tid & 127;
    bool doq = tid < 128;
    float v = doq ? g_qkv[qh*DH + t] : g_qkv[HQ*DH + kv*DH + t];
    float ss = warp_sum(v * v);
    if (lane == 0) { if (doq) redq[warp] = ss; else redk[warp - 4] = ss; }
    if (!doq) sv[t] = g_qkv[HQ*DH + HKV*DH + kv*DH + t];
    __syncthreads();
    float tot2 = doq ? (redq[0]+redq[1]+redq[2]+redq[3])
                     : (redk[0]+redk[1]+redk[2]+redk[3]);
    float inv = rsqrtf(tot2 / (float)DH + EPSR);
    float nv = v * inv * (doq ? qw[t] : kw[t]);
    if (doq) sq[t] = nv; else sk[t] = nv;
    __syncthreads();
    float partner;
    if (doq) partner = (t < DH/2) ? -sq[t + DH/2] : sq[t - DH/2];
    else     partner = (t < DH/2) ? -sk[t + DH/2] : sk[t - DH/2];
    float roped = nv * cosv[t] + partner * sinv[t];
    __syncthreads();
    if (doq) sq[t] = roped; else sk[t] = roped;
    __syncthreads();
    if (sp == 0 && (qh & 3) == 0 && !doq) {
        g_knew[kv*DH + t] = roped;
        g_vnew[kv*DH + t] = sv[t];
    }

    // ---- split-KV mainloop (batched 4 keys per warp iteration)
    float4 q = reinterpret_cast<const float4*>(sq)[lane];

    float m = -INFINITY, l = 0.f;
    float4 acc = make_float4(0.f, 0.f, 0.f, 0.f);
    for (int base = beg; base < end; base += 32) {
        float4 kx[4], vx[4];
        bool val[4];
        #pragma unroll
        for (int tt = 0; tt < 4; tt++) {
            int j = base + warp + 8*tt;
            val[tt] = (j < end);
            int jj = val[tt] ? j : beg;
            if (jj == p) {
                kx[tt] = reinterpret_cast<const float4*>(sk)[lane];
                vx[tt] = reinterpret_cast<const float4*>(sv)[lane];
            } else {
                kx[tt] = __ldg(reinterpret_cast<const float4*>(K + (size_t)jj * DH) + lane);
                vx[tt] = __ldg(reinterpret_cast<const float4*>(V + (size_t)jj * DH) + lane);
            }
        }
        float d[4];
        #pragma unroll
        for (int tt = 0; tt < 4; tt++)
            d[tt] = q.x*kx[tt].x + q.y*kx[tt].y + q.z*kx[tt].z + q.w*kx[tt].w;
        #pragma unroll
        for (int o = 16; o; o >>= 1) {
            #pragma unroll
            for (int tt = 0; tt < 4; tt++) d[tt] += __shfl_xor_sync(0xffffffffu, d[tt], o);
        }
        #pragma unroll
        for (int tt = 0; tt < 4; tt++) d[tt] = val[tt] ? d[tt] * scale : -INFINITY;
        float mb = fmaxf(fmaxf(d[0], d[1]), fmaxf(d[2], d[3]));
        if (mb > -INFINITY) {
            float mn = fmaxf(m, mb);
            float corr = (m > -INFINITY) ? __expf(m - mn) : 0.f;
            l *= corr;
            acc.x *= corr; acc.y *= corr; acc.z *= corr; acc.w *= corr;
            #pragma unroll
            for (int tt = 0; tt < 4; tt++) {
                if (val[tt]) {
                    float w = __expf(d[tt] - mn);
                    l += w;
                    acc.x += w * vx[tt].x; acc.y += w * vx[tt].y;
                    acc.z += w * vx[tt].z; acc.w += w * vx[tt].w;
                }
            }
            m = mn;
        }
    }

    // ---- block-level merge of 8 warps -> one partial
    __shared__ float s_m[8], s_l[8];
    __shared__ float s_acc[8][DH];
    if (lane == 0) { s_m[warp] = m; s_l[warp] = l; }
    s_acc[warp][4*lane + 0] = acc.x;
    s_acc[warp][4*lane + 1] = acc.y;
    s_acc[warp][4*lane + 2] = acc.z;
    s_acc[warp][4*lane + 3] = acc.w;
    __syncthreads();
    if (tid < DH) {
        int d = tid;
        float M = -INFINITY;
        #pragma unroll
        for (int w = 0; w < 8; w++) M = fmaxf(M, s_m[w]);
        float L = 0.f, A = 0.f;
        #pragma unroll
        for (int w = 0; w < 8; w++) {
            float f = (s_m[w] > -INFINITY) ? __expf(s_m[w] - M) : 0.f;
            L += s_l[w] * f;
            A += s_acc[w][d] * f;
        }
        g_pacc[(size_t)blockIdx.x * DH + d] = A;
        if (d == 0) { g_pm[blockIdx.x] = M; g_pl[blockIdx.x] = L; }
    }

    // ---- last block for this head merges all splits
    __shared__ int s_merge;
    __threadfence();
    __syncthreads();
    if (tid == 0) {
        int old = atomicAdd(&g_cnt[qh], 1);
        s_merge = (old == NSPL - 1);
        if (s_merge) g_cnt[qh] = 0;      // reset for next graph replay
    }
    __syncthreads();
    if (s_merge) {
        __threadfence();
        if (tid < DH) {
            int d = tid;
            float M = -INFINITY;
            #pragma unroll
            for (int s = 0; s < NSPL; s++) M = fmaxf(M, g_pm[qh*NSPL + s]);
            float L = 0.f, A = 0.f;
            #pragma unroll
            for (int s = 0; s < NSPL; s++) {
                float pm = g_pm[qh*NSPL + s];
                float f = (pm > -INFINITY) ? __expf(pm - M) : 0.f;
                L += g_pl[qh*NSPL + s] * f;
                A += g_pacc[(size_t)(qh*NSPL + s) * DH + d] * f;
            }
            g_attn[qh*DH + d] = A / L;
        }
    }
}

// ---------------- O projection + residual (1 row/warp) ----------------------
__global__ void gemv_o_k(const float* __restrict__ Wo, const float* __restrict__ resid) {
    cudaTriggerProgrammaticLaunchCompletion();
    __shared__ float4 sx[(HQ*DH)/4];
    int tid = threadIdx.x, warp = tid >> 5, lane = tid & 31;
    int r = blockIdx.x * 8 + warp;
    const float4* w4 = reinterpret_cast<const float4*>(Wo + (size_t)r * (HQ*DH));
    #pragma unroll
    for (int off = lane * 128; off < HQ*DH*4; off += 32 * 128)
        l2_prefetch((const char*)w4 + off);
    cudaGridDependencySynchronize();

    const float4* a4 = reinterpret_cast<const float4*>(g_attn);
    #pragma unroll
    for (int i = tid; i < (HQ*DH)/4; i += 256) sx[i] = a4[i];
    __syncthreads();
    float s = 0.f;
    #pragma unroll 8
    for (int i = lane; i < (HQ*DH)/4; i += 32) {
        float4 a = __ldcs(w4 + i); float4 b = sx[i];
        s += a.x*b.x + a.y*b.y + a.z*b.z + a.w*b.w;
    }
    s = warp_sum(s);
    if (lane == 0) g_h1[r] = resid[r] + s;
}

// ============ fused RMSNorm + gate/up GEMV (1 row/warp, 2 streams) =========
__global__ void gemv_gateup_k(const float* __restrict__ lnw,
                              const float* __restrict__ Wg, const float* __restrict__ Wu) {
    cudaTriggerProgrammaticLaunchCompletion();
    __shared__ float4 sx[HID/4];
    __shared__ float red[8];
    int tid = threadIdx.x, warp = tid >> 5, lane = tid & 31;
    int r = blockIdx.x * 8 + warp;
    const float4* g4 = reinterpret_cast<const float4*>(Wg + (size_t)r * HID);
    const float4* u4 = reinterpret_cast<const float4*>(Wu + (size_t)r * HID);
    #pragma unroll
    for (int off = lane * 128; off < HID*4; off += 32 * 128) {
        l2_prefetch((const char*)g4 + off);
        l2_prefetch((const char*)u4 + off);
    }
    cudaGridDependencySynchronize();

    const float4* x4 = reinterpret_cast<const float4*>(g_h1);
    const float4* w4 = reinterpret_cast<const float4*>(lnw);
    float ssq = 0.f;
    #pragma unroll
    for (int i = tid; i < HID/4; i += 256) {
        float4 v = x4[i];
        float4 w = __ldg(w4 + i);
        ssq += v.x*v.x + v.y*v.y + v.z*v.z + v.w*v.w;
        sx[i] = make_float4(v.x*w.x, v.y*w.y, v.z*w.z, v.w*w.w);
    }
    ssq = warp_sum(ssq);
    if (lane == 0) red[warp] = ssq;
    __syncthreads();

    float sg = 0.f, su = 0.f;
    #pragma unroll 8
    for (int i = lane; i < HID/4; i += 32) {
        float4 b = sx[i];
        float4 a = __ldcs(g4 + i);
        float4 c = __ldcs(u4 + i);
        sg += a.x*b.x + a.y*b.y + a.z*b.z + a.w*b.w;
        su += c.x*b.x + c.y*b.y + c.z*b.z + c.w*b.w;
    }
    sg = warp_sum(sg);
    su = warp_sum(su);
    if (lane == 0) {
        float tot = red[0]+red[1]+red[2]+red[3]+red[4]+red[5]+red[6]+red[7];
        float inv = rsqrtf(tot / (float)HID + EPSR);
        sg *= inv; su *= inv;
        g_m[r] = (sg / (1.f + __expf(-sg))) * su;
    }
}

// ---------------- down GEMV + residual (1 row/warp, 48KB smem) -------------
__global__ void gemv_down_k(const float* __restrict__ Wd, float* __restrict__ out) {
    cudaTriggerProgrammaticLaunchCompletion();
    __shared__ float4 sx[IM/4];          // 48 KB
    int tid = threadIdx.x, warp = tid >> 5, lane = tid & 31;
    int r = blockIdx.x * 8 + warp;
    const float4* w4 = reinterpret_cast<const float4*>(Wd + (size_t)r * IM);
    #pragma unroll
    for (int off = lane * 128; off < IM*4; off += 32 * 128)
        l2_prefetch((const char*)w4 + off);
    cudaGridDependencySynchronize();

    const float4* m4 = reinterpret_cast<const float4*>(g_m);
    #pragma unroll
    for (int i = tid; i < IM/4; i += 256) sx[i] = m4[i];
    __syncthreads();
    float s = 0.f;
    #pragma unroll 8
    for (int i = lane; i < IM/4; i += 32) {
        float4 a = __ldcs(w4 + i); float4 b = sx[i];
        s += a.x*b.x + a.y*b.y + a.z*b.z + a.w*b.w;
    }
    s = warp_sum(s);
    if (lane == 0) out[r] = g_h1[r] + s;
}

// ---------------- patch row `pos` of the copied caches ---------------------
__global__ void patch_k(const float* __restrict__ posp,
                        float* __restrict__ out_k, float* __restrict__ out_v) {
    cudaGridDependencySynchronize();
    int i = threadIdx.x;                 // 0..1023 = HKV*DH
    int head = i >> 7, t = i & 127;
    int p = (int)posp[0];
    size_t off = (size_t)head * SEQ * DH + (size_t)p * DH + t;
    out_k[off] = g_knew[i];
    out_v[off] = g_vnew[i];
}

// ---------------- PDL launch helper -----------------------------------------
template <typename... ExpTypes, typename... ActTypes>
static void launch_pdl(dim3 grid, dim3 block, void (*kernel)(ExpTypes...), ActTypes... args) {
    cudaLaunchConfig_t cfg = {};
    cfg.gridDim = grid;
    cfg.blockDim = block;
    cfg.dynamicSmemBytes = 0;
    cfg.stream = 0;
    cudaLaunchAttribute at[1];
    at[0].id = cudaLaunchAttributeProgrammaticStreamSerialization;
    at[0].val.programmaticStreamSerializationAllowed = 1;
    cfg.attrs = at;
    cfg.numAttrs = 1;
    cudaLaunchKernelEx(&cfg, kernel, (ExpTypes)args...);
}

// ---------------- launch ----------------------------------------------------
extern "C" void kernel_launch(void* const* d_in, const int* in_sizes, int n_in,
                              void* d_out, int out_size) {
    const float* x      = (const float*)d_in[0];
    const float* pos    = (const float*)d_in[1];
    const float* cosv   = (const float*)d_in[2];
    const float* sinv   = (const float*)d_in[3];
    const float* kcache = (const float*)d_in[4];
    const float* vcache = (const float*)d_in[5];
    const float* Wq     = (const float*)d_in[6];
    const float* Wk     = (const float*)d_in[7];
    const float* Wv     = (const float*)d_in[8];
    const float* Wo     = (const float*)d_in[9];
    const float* Wg     = (const float*)d_in[10];
    const float* Wu     = (const float*)d_in[11];
    const float* Wd     = (const float*)d_in[12];
    const float* qnw    = (const float*)d_in[13];
    const float* knw    = (const float*)d_in[14];
    const float* ln1w   = (const float*)d_in[15];
    const float* ln2w   = (const float*)d_in[16];

    float* out   = (float*)d_out;
    float* out_k = out + HID;
    float* out_v = out_k + (size_t)HKV * SEQ * DH;
    const size_t cache_bytes = (size_t)HKV * SEQ * DH * sizeof(float);

    static cudaStream_t s2 = nullptr;
    static cudaEvent_t ev_fork = nullptr, ev_join = nullptr;
    if (!s2) {
        cudaStreamCreateWithFlags(&s2, cudaStreamNonBlocking);
        cudaEventCreateWithFlags(&ev_fork, cudaEventDisableTiming);
        cudaEventCreateWithFlags(&ev_join, cudaEventDisableTiming);
    }

    // Fork: bulk cache copy runs concurrently with the whole compute pipeline.
    cudaEventRecord(ev_fork, 0);
    cudaStreamWaitEvent(s2, ev_fork, 0);
    cudaMemcpyAsync(out_k, kcache, cache_bytes, cudaMemcpyDeviceToDevice, s2);
    cudaMemcpyAsync(out_v, vcache, cache_bytes, cudaMemcpyDeviceToDevice, s2);
    cudaEventRecord(ev_join, s2);

    gemv_qkv_k<<<(HQ*DH + 2*HKV*DH) / 8, 256>>>(x, ln1w, Wq, Wk, Wv);
    launch_pdl(dim3(HQ * NSPL), dim3(256), attn_k, pos, kcache, vcache, cosv, sinv, qnw, knw);
    launch_pdl(dim3(HID / 8), dim3(256), gemv_o_k, Wo, x);
    launch_pdl(dim3(IM / 8), dim3(256), gemv_gateup_k, ln2w, Wg, Wu);
    launch_pdl(dim3(HID / 8), dim3(256), gemv_down_k, Wd, out);

    // Join: patch the freshly written row into the copied caches.
    cudaStreamWaitEvent(0, ev_join, 0);
    patch_k<<<1, HKV * DH>>>(pos, out_k, out_v);
}

// round 10
// speedup vs baseline: 1.1014x; 1.0821x over previous
#include <cuda_runtime.h>
#include <math.h>
#include <stdint.h>

#define HQ   32
#define HKV  8
#define DH   128
#define HID  4096
#define IM   12288
#define SEQ  8192
#define EPSR 1e-6f
#define NSPL 16           // KV splits per head for flash decoding

// ---------------- scratch (device globals; no allocation allowed) ----------
__device__ __align__(16) float g_qkv[HQ*DH + 2*HKV*DH];  // q | k | v raw projections
__device__ __align__(16) float g_knew[HKV*DH];           // new K row (post rope)
__device__ __align__(16) float g_vnew[HKV*DH];           // new V row
__device__ __align__(16) float g_attn[HQ*DH];            // attention output
__device__ __align__(16) float g_h1[HID];                // residual + o_proj
__device__ __align__(16) float g_h1w[HID];               // h1 * ln2w (pre-scaled)
__device__ __align__(16) float g_m[IM];                  // silu(gate)*up
__device__ float g_ssq;                                  // sum(h1^2); zeroed by attn_k
// split-KV partials + completion counters
__device__ __align__(16) float g_pacc[HQ*NSPL*DH];
__device__ float g_pm[HQ*NSPL];
__device__ float g_pl[HQ*NSPL];
__device__ int   g_cnt[HQ];                              // zero-init; self-resetting

// ---------------- helpers --------------------------------------------------
__device__ __forceinline__ float warp_sum(float v) {
    #pragma unroll
    for (int o = 16; o; o >>= 1) v += __shfl_xor_sync(0xffffffffu, v, o);
    return v;
}

// ============ fused RMSNorm + QKV GEMV (1 row/warp) ========================
__global__ void gemv_qkv_k(const float* __restrict__ x, const float* __restrict__ lnw,
                           const float* __restrict__ Wq, const float* __restrict__ Wk,
                           const float* __restrict__ Wv) {
    __shared__ float4 sx[HID/4];
    __shared__ float red[8];
    int tid = threadIdx.x, warp = tid >> 5, lane = tid & 31;
    const float4* x4 = reinterpret_cast<const float4*>(x);
    const float4* w4 = reinterpret_cast<const float4*>(lnw);
    float ssq = 0.f;
    #pragma unroll
    for (int i = tid; i < HID/4; i += 256) {
        float4 v = __ldg(x4 + i);
        float4 w = __ldg(w4 + i);
        ssq += v.x*v.x + v.y*v.y + v.z*v.z + v.w*v.w;
        sx[i] = make_float4(v.x*w.x, v.y*w.y, v.z*w.z, v.w*w.w);
    }
    ssq = warp_sum(ssq);
    if (lane == 0) red[warp] = ssq;
    __syncthreads();

    int r = blockIdx.x * 8 + warp;
    const float* row;
    if (r < HQ*DH)                  row = Wq + (size_t)r * HID;
    else if (r < HQ*DH + HKV*DH)    row = Wk + (size_t)(r - HQ*DH) * HID;
    else                            row = Wv + (size_t)(r - HQ*DH - HKV*DH) * HID;
    const float4* wr = reinterpret_cast<const float4*>(row);
    float s = 0.f;
    #pragma unroll 8
    for (int i = lane; i < HID/4; i += 32) {
        float4 a = __ldcs(wr + i); float4 b = sx[i];
        s += a.x*b.x + a.y*b.y + a.z*b.z + a.w*b.w;
    }
    s = warp_sum(s);
    if (lane == 0) {
        float tot = red[0]+red[1]+red[2]+red[3]+red[4]+red[5]+red[6]+red[7];
        g_qkv[r] = s * rsqrtf(tot / (float)HID + EPSR);
    }
}

// ============ attention: fused rope + split-KV partials + last-block merge =
__global__ void attn_k(const float* __restrict__ posp,
                       const float* __restrict__ Kc, const float* __restrict__ Vc,
                       const float* __restrict__ cosv, const float* __restrict__ sinv,
                       const float* __restrict__ qw, const float* __restrict__ kw) {
    const float scale = 0.088388347648318447f;  // 128^-0.5
    int qh = blockIdx.x / NSPL;
    int sp = blockIdx.x % NSPL;
    int kv = qh >> 2;
    int tid = threadIdx.x;
    int warp = tid >> 5, lane = tid & 31;

    if (blockIdx.x == 0 && tid == 0) g_ssq = 0.f;   // reset for gemv_o epilogue

    __shared__ __align__(16) float sq[DH], sk[DH], sv[DH];
    __shared__ float redq[4], redk[4];

    // ---- prologue: per-head RMSNorm + RoPE (threads 0-127: q, 128-255: k/v)
    int t = tid & 127;
    bool doq = tid < 128;
    float v = doq ? g_qkv[qh*DH + t] : g_qkv[HQ*DH + kv*DH + t];
    float ss = warp_sum(v * v);
    if (lane == 0) { if (doq) redq[warp] = ss; else redk[warp - 4] = ss; }
    if (!doq) sv[t] = g_qkv[HQ*DH + HKV*DH + kv*DH + t];
    __syncthreads();
    float tot = doq ? (redq[0]+redq[1]+redq[2]+redq[3])
                    : (redk[0]+redk[1]+redk[2]+redk[3]);
    float inv = rsqrtf(tot / (float)DH + EPSR);
    float nv = v * inv * (doq ? qw[t] : kw[t]);
    if (doq) sq[t] = nv; else sk[t] = nv;
    __syncthreads();
    float partner;
    if (doq) partner = (t < DH/2) ? -sq[t + DH/2] : sq[t - DH/2];
    else     partner = (t < DH/2) ? -sk[t + DH/2] : sk[t - DH/2];
    float roped = nv * cosv[t] + partner * sinv[t];
    __syncthreads();
    if (doq) sq[t] = roped; else sk[t] = roped;
    __syncthreads();
    if (sp == 0 && (qh & 3) == 0 && !doq) {
        g_knew[kv*DH + t] = roped;
        g_vnew[kv*DH + t] = sv[t];
    }

    // ---- split-KV mainloop (batched 4 keys per warp iteration)
    int p = (int)posp[0];
    int total = p + 1;
    int chunk = (total + NSPL - 1) / NSPL;
    int beg = sp * chunk;
    int end = min(beg + chunk, total);
    const float* K = Kc + (size_t)kv * SEQ * DH;
    const float* V = Vc + (size_t)kv * SEQ * DH;
    float4 q = reinterpret_cast<const float4*>(sq)[lane];

    float m = -INFINITY, l = 0.f;
    float4 acc = make_float4(0.f, 0.f, 0.f, 0.f);
    for (int base = beg; base < end; base += 32) {
        float4 kx[4], vx[4];
        bool val[4];
        #pragma unroll
        for (int tt = 0; tt < 4; tt++) {
            int j = base + warp + 8*tt;
            val[tt] = (j < end);
            int jj = val[tt] ? j : beg;
            if (jj == p) {
                kx[tt] = reinterpret_cast<const float4*>(sk)[lane];
                vx[tt] = reinterpret_cast<const float4*>(sv)[lane];
            } else {
                kx[tt] = __ldg(reinterpret_cast<const float4*>(K + (size_t)jj * DH) + lane);
                vx[tt] = __ldg(reinterpret_cast<const float4*>(V + (size_t)jj * DH) + lane);
            }
        }
        float d[4];
        #pragma unroll
        for (int tt = 0; tt < 4; tt++)
            d[tt] = q.x*kx[tt].x + q.y*kx[tt].y + q.z*kx[tt].z + q.w*kx[tt].w;
        #pragma unroll
        for (int o = 16; o; o >>= 1) {
            #pragma unroll
            for (int tt = 0; tt < 4; tt++) d[tt] += __shfl_xor_sync(0xffffffffu, d[tt], o);
        }
        #pragma unroll
        for (int tt = 0; tt < 4; tt++) d[tt] = val[tt] ? d[tt] * scale : -INFINITY;
        float mb = fmaxf(fmaxf(d[0], d[1]), fmaxf(d[2], d[3]));
        if (mb > -INFINITY) {
            float mn = fmaxf(m, mb);
            float corr = (m > -INFINITY) ? __expf(m - mn) : 0.f;
            l *= corr;
            acc.x *= corr; acc.y *= corr; acc.z *= corr; acc.w *= corr;
            #pragma unroll
            for (int tt = 0; tt < 4; tt++) {
                if (val[tt]) {
                    float w = __expf(d[tt] - mn);
                    l += w;
                    acc.x += w * vx[tt].x; acc.y += w * vx[tt].y;
                    acc.z += w * vx[tt].z; acc.w += w * vx[tt].w;
                }
            }
            m = mn;
        }
    }

    // ---- block-level merge of 8 warps -> one partial
    __shared__ float s_m[8], s_l[8];
    __shared__ float s_acc[8][DH];
    if (lane == 0) { s_m[warp] = m; s_l[warp] = l; }
    s_acc[warp][4*lane + 0] = acc.x;
    s_acc[warp][4*lane + 1] = acc.y;
    s_acc[warp][4*lane + 2] = acc.z;
    s_acc[warp][4*lane + 3] = acc.w;
    __syncthreads();
    if (tid < DH) {
        int d = tid;
        float M = -INFINITY;
        #pragma unroll
        for (int w = 0; w < 8; w++) M = fmaxf(M, s_m[w]);
        float L = 0.f, A = 0.f;
        #pragma unroll
        for (int w = 0; w < 8; w++) {
            float f = (s_m[w] > -INFINITY) ? __expf(s_m[w] - M) : 0.f;
            L += s_l[w] * f;
            A += s_acc[w][d] * f;
        }
        g_pacc[(size_t)blockIdx.x * DH + d] = A;
        if (d == 0) { g_pm[blockIdx.x] = M; g_pl[blockIdx.x] = L; }
    }

    // ---- last block for this head merges all splits
    __shared__ int s_merge;
    __threadfence();
    __syncthreads();
    if (tid == 0) {
        int old = atomicAdd(&g_cnt[qh], 1);
        s_merge = (old == NSPL - 1);
        if (s_merge) g_cnt[qh] = 0;      // reset for next graph replay
    }
    __syncthreads();
    if (s_merge) {
        __threadfence();
        if (tid < DH) {
            int d = tid;
            float M = -INFINITY;
            #pragma unroll
            for (int s = 0; s < NSPL; s++) M = fmaxf(M, g_pm[qh*NSPL + s]);
            float L = 0.f, A = 0.f;
            #pragma unroll
            for (int s = 0; s < NSPL; s++) {
                float pm = g_pm[qh*NSPL + s];
                float f = (pm > -INFINITY) ? __expf(pm - M) : 0.f;
                L += g_pl[qh*NSPL + s] * f;
                A += g_pacc[(size_t)(qh*NSPL + s) * DH + d] * f;
            }
            g_attn[qh*DH + d] = A / L;
        }
    }
}

// ---------------- O projection + residual + ln2 pre-scale ------------------
// Writes h1, h1*ln2w, and accumulates sum(h1^2) into g_ssq (one atomic/block).
__global__ void gemv_o_k(const float* __restrict__ Wo, const float* __restrict__ resid,
                         const float* __restrict__ ln2w) {
    __shared__ float4 sx[(HQ*DH)/4];
    __shared__ float sh1[8];
    int tid = threadIdx.x, warp = tid >> 5, lane = tid & 31;
    const float4* a4 = reinterpret_cast<const float4*>(g_attn);
    #pragma unroll
    for (int i = tid; i < (HQ*DH)/4; i += 256) sx[i] = a4[i];
    __syncthreads();
    int r = blockIdx.x * 8 + warp;
    const float4* w4 = reinterpret_cast<const float4*>(Wo + (size_t)r * (HQ*DH));
    float s = 0.f;
    #pragma unroll 8
    for (int i = lane; i < (HQ*DH)/4; i += 32) {
        float4 a = __ldcs(w4 + i); float4 b = sx[i];
        s += a.x*b.x + a.y*b.y + a.z*b.z + a.w*b.w;
    }
    s = warp_sum(s);
    if (lane == 0) {
        float h1 = resid[r] + s;
        g_h1[r] = h1;
        g_h1w[r] = h1 * ln2w[r];
        sh1[warp] = h1 * h1;
    }
    __syncthreads();
    if (tid == 0) {
        float t = sh1[0]+sh1[1]+sh1[2]+sh1[3]+sh1[4]+sh1[5]+sh1[6]+sh1[7];
        atomicAdd(&g_ssq, t);
    }
}

// ============ gate/up GEMV: pre-scaled input, scalar inv from g_ssq ========
__global__ void gemv_gateup_k(const float* __restrict__ Wg, const float* __restrict__ Wu) {
    __shared__ float4 sx[HID/4];
    int tid = threadIdx.x, warp = tid >> 5, lane = tid & 31;
    const float4* x4 = reinterpret_cast<const float4*>(g_h1w);
    #pragma unroll
    for (int i = tid; i < HID/4; i += 256) sx[i] = x4[i];
    __syncthreads();

    int r = blockIdx.x * 8 + warp;
    const float4* g4 = reinterpret_cast<const float4*>(Wg + (size_t)r * HID);
    const float4* u4 = reinterpret_cast<const float4*>(Wu + (size_t)r * HID);
    float sg = 0.f, su = 0.f;
    #pragma unroll 8
    for (int i = lane; i < HID/4; i += 32) {
        float4 b = sx[i];
        float4 a = __ldcs(g4 + i);
        float4 c = __ldcs(u4 + i);
        sg += a.x*b.x + a.y*b.y + a.z*b.z + a.w*b.w;
        su += c.x*b.x + c.y*b.y + c.z*b.z + c.w*b.w;
    }
    sg = warp_sum(sg);
    su = warp_sum(su);
    if (lane == 0) {
        float inv = rsqrtf(g_ssq / (float)HID + EPSR);
        sg *= inv; su *= inv;
        g_m[r] = (sg / (1.f + __expf(-sg))) * su;
    }
}

// ---------------- down GEMV + residual (48KB smem staging) -----------------
__global__ void gemv_down_k(const float* __restrict__ Wd, float* __restrict__ out) {
    __shared__ float4 sx[IM/4];          // 48 KB
    int tid = threadIdx.x, warp = tid >> 5, lane = tid & 31;
    const float4* m4 = reinterpret_cast<const float4*>(g_m);
    #pragma unroll
    for (int i = tid; i < IM/4; i += 256) sx[i] = m4[i];
    __syncthreads();
    int r = blockIdx.x * 8 + warp;
    const float4* w4 = reinterpret_cast<const float4*>(Wd + (size_t)r * IM);
    float s = 0.f;
    #pragma unroll 8
    for (int i = lane; i < IM/4; i += 32) {
        float4 a = __ldcs(w4 + i); float4 b = sx[i];
        s += a.x*b.x + a.y*b.y + a.z*b.z + a.w*b.w;
    }
    s = warp_sum(s);
    if (lane == 0) out[r] = g_h1[r] + s;
}

// ---------------- patch row `pos` of the copied caches ---------------------
__global__ void patch_k(const float* __restrict__ posp,
                        float* __restrict__ out_k, float* __restrict__ out_v) {
    int i = threadIdx.x;                 // 0..1023 = HKV*DH
    int head = i >> 7, t = i & 127;
    int p = (int)posp[0];
    size_t off = (size_t)head * SEQ * DH + (size_t)p * DH + t;
    out_k[off] = g_knew[i];
    out_v[off] = g_vnew[i];
}

// ---------------- launch ----------------------------------------------------
extern "C" void kernel_launch(void* const* d_in, const int* in_sizes, int n_in,
                              void* d_out, int out_size) {
    const float* x      = (const float*)d_in[0];
    const float* pos    = (const float*)d_in[1];
    const float* cosv   = (const float*)d_in[2];
    const float* sinv   = (const float*)d_in[3];
    const float* kcache = (const float*)d_in[4];
    const float* vcache = (const float*)d_in[5];
    const float* Wq     = (const float*)d_in[6];
    const float* Wk     = (const float*)d_in[7];
    const float* Wv     = (const float*)d_in[8];
    const float* Wo     = (const float*)d_in[9];
    const float* Wg     = (const float*)d_in[10];
    const float* Wu     = (const float*)d_in[11];
    const float* Wd     = (const float*)d_in[12];
    const float* qnw    = (const float*)d_in[13];
    const float* knw    = (const float*)d_in[14];
    const float* ln1w   = (const float*)d_in[15];
    const float* ln2w   = (const float*)d_in[16];

    float* out   = (float*)d_out;
    float* out_k = out + HID;
    float* out_v = out_k + (size_t)HKV * SEQ * DH;
    const size_t cache_bytes = (size_t)HKV * SEQ * DH * sizeof(float);

    static cudaStream_t s2 = nullptr;
    static cudaEvent_t ev_fork = nullptr, ev_join = nullptr;
    if (!s2) {
        cudaStreamCreateWithFlags(&s2, cudaStreamNonBlocking);
        cudaEventCreateWithFlags(&ev_fork, cudaEventDisableTiming);
        cudaEventCreateWithFlags(&ev_join, cudaEventDisableTiming);
    }

    // Fork: bulk cache copy runs concurrently with the whole compute pipeline.
    cudaEventRecord(ev_fork, 0);
    cudaStreamWaitEvent(s2, ev_fork, 0);
    cudaMemcpyAsync(out_k, kcache, cache_bytes, cudaMemcpyDeviceToDevice, s2);
    cudaMemcpyAsync(out_v, vcache, cache_bytes, cudaMemcpyDeviceToDevice, s2);
    cudaEventRecord(ev_join, s2);

    gemv_qkv_k<<<(HQ*DH + 2*HKV*DH) / 8, 256>>>(x, ln1w, Wq, Wk, Wv);
    attn_k<<<HQ * NSPL, 256>>>(pos, kcache, vcache, cosv, sinv, qnw, knw);
    gemv_o_k<<<HID / 8, 256>>>(Wo, x, ln2w);
    gemv_gateup_k<<<IM / 8, 256>>>(Wg, Wu);
    gemv_down_k<<<HID / 8, 256>>>(Wd, out);

    // Join: patch the freshly written row into the copied caches.
    cudaStreamWaitEvent(0, ev_join, 0);
    patch_k<<<1, HKV * DH>>>(pos, out_k, out_v);
}

// round 11
// speedup vs baseline: 1.1503x; 1.0444x over previous
#include <cuda_runtime.h>
#include <math.h>
#include <stdint.h>

#define HQ   32
#define HKV  8
#define DH   128
#define HID  4096
#define IM   12288
#define SEQ  8192
#define EPSR 1e-6f
#define NSPL 16           // KV splits per head for flash decoding

// ---------------- scratch (device globals; no allocation allowed) ----------
__device__ __align__(16) float g_qkv[HQ*DH + 2*HKV*DH];  // q | k | v raw projections
__device__ __align__(16) float g_knew[HKV*DH];           // new K row (post rope)
__device__ __align__(16) float g_vnew[HKV*DH];           // new V row
__device__ __align__(16) float g_attn[HQ*DH];            // attention output
__device__ __align__(16) float g_h1[HID];                // residual + o_proj
__device__ __align__(16) float g_h1w[HID];               // h1 * ln2w (pre-scaled)
__device__ __align__(16) float g_m[IM];                  // silu(gate)*up
__device__ __align__(16) float g_dpart[2][HID];          // down-proj split-K partials
__device__ float g_ssq;                                  // sum(h1^2); zeroed by attn_k
// split-KV partials + completion counters
__device__ __align__(16) float g_pacc[HQ*NSPL*DH];
__device__ float g_pm[HQ*NSPL];
__device__ float g_pl[HQ*NSPL];
__device__ int   g_cnt[HQ];                              // zero-init; self-resetting

// ---------------- helpers --------------------------------------------------
__device__ __forceinline__ float warp_sum(float v) {
    #pragma unroll
    for (int o = 16; o; o >>= 1) v += __shfl_xor_sync(0xffffffffu, v, o);
    return v;
}

// ============ fused RMSNorm + QKV GEMV (1 row/warp) ========================
__global__ void __launch_bounds__(256, 6)
gemv_qkv_k(const float* __restrict__ x, const float* __restrict__ lnw,
           const float* __restrict__ Wq, const float* __restrict__ Wk,
           const float* __restrict__ Wv) {
    __shared__ float4 sx[HID/4];
    __shared__ float red[8];
    int tid = threadIdx.x, warp = tid >> 5, lane = tid & 31;
    const float4* x4 = reinterpret_cast<const float4*>(x);
    const float4* w4 = reinterpret_cast<const float4*>(lnw);
    float ssq = 0.f;
    #pragma unroll
    for (int i = tid; i < HID/4; i += 256) {
        float4 v = __ldg(x4 + i);
        float4 w = __ldg(w4 + i);
        ssq += v.x*v.x + v.y*v.y + v.z*v.z + v.w*v.w;
        sx[i] = make_float4(v.x*w.x, v.y*w.y, v.z*w.z, v.w*w.w);
    }
    ssq = warp_sum(ssq);
    if (lane == 0) red[warp] = ssq;
    __syncthreads();

    int r = blockIdx.x * 8 + warp;
    const float* row;
    if (r < HQ*DH)                  row = Wq + (size_t)r * HID;
    else if (r < HQ*DH + HKV*DH)    row = Wk + (size_t)(r - HQ*DH) * HID;
    else                            row = Wv + (size_t)(r - HQ*DH - HKV*DH) * HID;
    const float4* wr = reinterpret_cast<const float4*>(row);
    float s = 0.f;
    #pragma unroll 8
    for (int i = lane; i < HID/4; i += 32) {
        float4 a = __ldcs(wr + i); float4 b = sx[i];
        s += a.x*b.x + a.y*b.y + a.z*b.z + a.w*b.w;
    }
    s = warp_sum(s);
    if (lane == 0) {
        float tot = red[0]+red[1]+red[2]+red[3]+red[4]+red[5]+red[6]+red[7];
        g_qkv[r] = s * rsqrtf(tot / (float)HID + EPSR);
    }
}

// ============ attention: fused rope + split-KV partials + last-block merge =
__global__ void attn_k(const float* __restrict__ posp,
                       const float* __restrict__ Kc, const float* __restrict__ Vc,
                       const float* __restrict__ cosv, const float* __restrict__ sinv,
                       const float* __restrict__ qw, const float* __restrict__ kw) {
    const float scale = 0.088388347648318447f;  // 128^-0.5
    int qh = blockIdx.x / NSPL;
    int sp = blockIdx.x % NSPL;
    int kv = qh >> 2;
    int tid = threadIdx.x;
    int warp = tid >> 5, lane = tid & 31;

    if (blockIdx.x == 0 && tid == 0) g_ssq = 0.f;   // reset for gemv_o epilogue

    __shared__ __align__(16) float sq[DH], sk[DH], sv[DH];
    __shared__ float redq[4], redk[4];

    // ---- prologue: per-head RMSNorm + RoPE (threads 0-127: q, 128-255: k/v)
    int t = tid & 127;
    bool doq = tid < 128;
    float v = doq ? g_qkv[qh*DH + t] : g_qkv[HQ*DH + kv*DH + t];
    float ss = warp_sum(v * v);
    if (lane == 0) { if (doq) redq[warp] = ss; else redk[warp - 4] = ss; }
    if (!doq) sv[t] = g_qkv[HQ*DH + HKV*DH + kv*DH + t];
    __syncthreads();
    float tot = doq ? (redq[0]+redq[1]+redq[2]+redq[3])
                    : (redk[0]+redk[1]+redk[2]+redk[3]);
    float inv = rsqrtf(tot / (float)DH + EPSR);
    float nv = v * inv * (doq ? qw[t] : kw[t]);
    if (doq) sq[t] = nv; else sk[t] = nv;
    __syncthreads();
    float partner;
    if (doq) partner = (t < DH/2) ? -sq[t + DH/2] : sq[t - DH/2];
    else     partner = (t < DH/2) ? -sk[t + DH/2] : sk[t - DH/2];
    float roped = nv * cosv[t] + partner * sinv[t];
    __syncthreads();
    if (doq) sq[t] = roped; else sk[t] = roped;
    __syncthreads();
    if (sp == 0 && (qh & 3) == 0 && !doq) {
        g_knew[kv*DH + t] = roped;
        g_vnew[kv*DH + t] = sv[t];
    }

    // ---- split-KV mainloop (batched 4 keys per warp iteration)
    int p = (int)posp[0];
    int total = p + 1;
    int chunk = (total + NSPL - 1) / NSPL;
    int beg = sp * chunk;
    int end = min(beg + chunk, total);
    const float* K = Kc + (size_t)kv * SEQ * DH;
    const float* V = Vc + (size_t)kv * SEQ * DH;
    float4 q = reinterpret_cast<const float4*>(sq)[lane];

    float m = -INFINITY, l = 0.f;
    float4 acc = make_float4(0.f, 0.f, 0.f, 0.f);
    for (int base = beg; base < end; base += 32) {
        float4 kx[4], vx[4];
        bool val[4];
        #pragma unroll
        for (int tt = 0; tt < 4; tt++) {
            int j = base + warp + 8*tt;
            val[tt] = (j < end);
            int jj = val[tt] ? j : beg;
            if (jj == p) {
                kx[tt] = reinterpret_cast<const float4*>(sk)[lane];
                vx[tt] = reinterpret_cast<const float4*>(sv)[lane];
            } else {
                kx[tt] = __ldg(reinterpret_cast<const float4*>(K + (size_t)jj * DH) + lane);
                vx[tt] = __ldg(reinterpret_cast<const float4*>(V + (size_t)jj * DH) + lane);
            }
        }
        float d[4];
        #pragma unroll
        for (int tt = 0; tt < 4; tt++)
            d[tt] = q.x*kx[tt].x + q.y*kx[tt].y + q.z*kx[tt].z + q.w*kx[tt].w;
        #pragma unroll
        for (int o = 16; o; o >>= 1) {
            #pragma unroll
            for (int tt = 0; tt < 4; tt++) d[tt] += __shfl_xor_sync(0xffffffffu, d[tt], o);
        }
        #pragma unroll
        for (int tt = 0; tt < 4; tt++) d[tt] = val[tt] ? d[tt] * scale : -INFINITY;
        float mb = fmaxf(fmaxf(d[0], d[1]), fmaxf(d[2], d[3]));
        if (mb > -INFINITY) {
            float mn = fmaxf(m, mb);
            float corr = (m > -INFINITY) ? __expf(m - mn) : 0.f;
            l *= corr;
            acc.x *= corr; acc.y *= corr; acc.z *= corr; acc.w *= corr;
            #pragma unroll
            for (int tt = 0; tt < 4; tt++) {
                if (val[tt]) {
                    float w = __expf(d[tt] - mn);
                    l += w;
                    acc.x += w * vx[tt].x; acc.y += w * vx[tt].y;
                    acc.z += w * vx[tt].z; acc.w += w * vx[tt].w;
                }
            }
            m = mn;
        }
    }

    // ---- block-level merge of 8 warps -> one partial
    __shared__ float s_m[8], s_l[8];
    __shared__ float s_acc[8][DH];
    if (lane == 0) { s_m[warp] = m; s_l[warp] = l; }
    s_acc[warp][4*lane + 0] = acc.x;
    s_acc[warp][4*lane + 1] = acc.y;
    s_acc[warp][4*lane + 2] = acc.z;
    s_acc[warp][4*lane + 3] = acc.w;
    __syncthreads();
    if (tid < DH) {
        int d = tid;
        float M = -INFINITY;
        #pragma unroll
        for (int w = 0; w < 8; w++) M = fmaxf(M, s_m[w]);
        float L = 0.f, A = 0.f;
        #pragma unroll
        for (int w = 0; w < 8; w++) {
            float f = (s_m[w] > -INFINITY) ? __expf(s_m[w] - M) : 0.f;
            L += s_l[w] * f;
            A += s_acc[w][d] * f;
        }
        g_pacc[(size_t)blockIdx.x * DH + d] = A;
        if (d == 0) { g_pm[blockIdx.x] = M; g_pl[blockIdx.x] = L; }
    }

    // ---- last block for this head merges all splits
    __shared__ int s_merge;
    __threadfence();
    __syncthreads();
    if (tid == 0) {
        int old = atomicAdd(&g_cnt[qh], 1);
        s_merge = (old == NSPL - 1);
        if (s_merge) g_cnt[qh] = 0;      // reset for next graph replay
    }
    __syncthreads();
    if (s_merge) {
        __threadfence();
        if (tid < DH) {
            int d = tid;
            float M = -INFINITY;
            #pragma unroll
            for (int s = 0; s < NSPL; s++) M = fmaxf(M, g_pm[qh*NSPL + s]);
            float L = 0.f, A = 0.f;
            #pragma unroll
            for (int s = 0; s < NSPL; s++) {
                float pm = g_pm[qh*NSPL + s];
                float f = (pm > -INFINITY) ? __expf(pm - M) : 0.f;
                L += g_pl[qh*NSPL + s] * f;
                A += g_pacc[(size_t)(qh*NSPL + s) * DH + d] * f;
            }
            g_attn[qh*DH + d] = A / L;
        }
    }
}

// ---------------- O projection + residual + ln2 pre-scale ------------------
__global__ void __launch_bounds__(256, 6)
gemv_o_k(const float* __restrict__ Wo, const float* __restrict__ resid,
         const float* __restrict__ ln2w) {
    __shared__ float4 sx[(HQ*DH)/4];
    __shared__ float sh1[8];
    int tid = threadIdx.x, warp = tid >> 5, lane = tid & 31;
    const float4* a4 = reinterpret_cast<const float4*>(g_attn);
    #pragma unroll
    for (int i = tid; i < (HQ*DH)/4; i += 256) sx[i] = a4[i];
    __syncthreads();
    int r = blockIdx.x * 8 + warp;
    const float4* w4 = reinterpret_cast<const float4*>(Wo + (size_t)r * (HQ*DH));
    float s = 0.f;
    #pragma unroll 8
    for (int i = lane; i < (HQ*DH)/4; i += 32) {
        float4 a = __ldcs(w4 + i); float4 b = sx[i];
        s += a.x*b.x + a.y*b.y + a.z*b.z + a.w*b.w;
    }
    s = warp_sum(s);
    if (lane == 0) {
        float h1 = resid[r] + s;
        g_h1[r] = h1;
        g_h1w[r] = h1 * ln2w[r];
        sh1[warp] = h1 * h1;
    }
    __syncthreads();
    if (tid == 0) {
        float t = sh1[0]+sh1[1]+sh1[2]+sh1[3]+sh1[4]+sh1[5]+sh1[6]+sh1[7];
        atomicAdd(&g_ssq, t);
    }
}

// ============ gate/up GEMV: pre-scaled input, scalar inv from g_ssq ========
__global__ void __launch_bounds__(256, 6)
gemv_gateup_k(const float* __restrict__ Wg, const float* __restrict__ Wu) {
    __shared__ float4 sx[HID/4];
    int tid = threadIdx.x, warp = tid >> 5, lane = tid & 31;
    const float4* x4 = reinterpret_cast<const float4*>(g_h1w);
    #pragma unroll
    for (int i = tid; i < HID/4; i += 256) sx[i] = x4[i];
    __syncthreads();

    int r = blockIdx.x * 8 + warp;
    const float4* g4 = reinterpret_cast<const float4*>(Wg + (size_t)r * HID);
    const float4* u4 = reinterpret_cast<const float4*>(Wu + (size_t)r * HID);
    float sg = 0.f, su = 0.f;
    #pragma unroll 8
    for (int i = lane; i < HID/4; i += 32) {
        float4 b = sx[i];
        float4 a = __ldcs(g4 + i);
        float4 c = __ldcs(u4 + i);
        sg += a.x*b.x + a.y*b.y + a.z*b.z + a.w*b.w;
        su += c.x*b.x + c.y*b.y + c.z*b.z + c.w*b.w;
    }
    sg = warp_sum(sg);
    su = warp_sum(su);
    if (lane == 0) {
        float inv = rsqrtf(g_ssq / (float)HID + EPSR);
        sg *= inv; su *= inv;
        g_m[r] = (sg / (1.f + __expf(-sg))) * su;
    }
}

// ---------------- down GEMV, split-K by 2 (24KB smem, 1024 blocks) ---------
// Block b: rows (b>>1)*8 + warp, K-half = b&1. Partial into g_dpart.
__global__ void __launch_bounds__(256, 6)
gemv_down_k(const float* __restrict__ Wd) {
    __shared__ float4 sx[IM/8];          // 24 KB: one half of g_m
    int tid = threadIdx.x, warp = tid >> 5, lane = tid & 31;
    int half = blockIdx.x & 1;
    int base4 = half * (IM/8);           // offset in float4 units
    const float4* m4 = reinterpret_cast<const float4*>(g_m) + base4;
    #pragma unroll
    for (int i = tid; i < IM/8; i += 256) sx[i] = m4[i];
    __syncthreads();
    int r = (blockIdx.x >> 1) * 8 + warp;
    const float4* w4 = reinterpret_cast<const float4*>(Wd + (size_t)r * IM) + base4;
    float s = 0.f;
    #pragma unroll 8
    for (int i = lane; i < IM/8; i += 32) {
        float4 a = __ldcs(w4 + i); float4 b = sx[i];
        s += a.x*b.x + a.y*b.y + a.z*b.z + a.w*b.w;
    }
    s = warp_sum(s);
    if (lane == 0) g_dpart[half][r] = s;
}

// ---------------- finish: combine down halves + patch cache row ------------
// grid = 20 x 256: blocks 0-15 -> out combine (4096), blocks 16-19 -> patch.
__global__ void finish_k(const float* __restrict__ posp,
                         float* __restrict__ out,
                         float* __restrict__ out_k, float* __restrict__ out_v) {
    int gi = blockIdx.x * 256 + threadIdx.x;
    if (blockIdx.x < 16) {
        out[gi] = g_h1[gi] + g_dpart[0][gi] + g_dpart[1][gi];
    } else {
        int i = gi - 16*256;             // 0..1023 = HKV*DH
        int head = i >> 7, t = i & 127;
        int p = (int)posp[0];
        size_t off = (size_t)head * SEQ * DH + (size_t)p * DH + t;
        out_k[off] = g_knew[i];
        out_v[off] = g_vnew[i];
    }
}

// ---------------- launch ----------------------------------------------------
extern "C" void kernel_launch(void* const* d_in, const int* in_sizes, int n_in,
                              void* d_out, int out_size) {
    const float* x      = (const float*)d_in[0];
    const float* pos    = (const float*)d_in[1];
    const float* cosv   = (const float*)d_in[2];
    const float* sinv   = (const float*)d_in[3];
    const float* kcache = (const float*)d_in[4];
    const float* vcache = (const float*)d_in[5];
    const float* Wq     = (const float*)d_in[6];
    const float* Wk     = (const float*)d_in[7];
    const float* Wv     = (const float*)d_in[8];
    const float* Wo     = (const float*)d_in[9];
    const float* Wg     = (const float*)d_in[10];
    const float* Wu     = (const float*)d_in[11];
    const float* Wd     = (const float*)d_in[12];
    const float* qnw    = (const float*)d_in[13];
    const float* knw    = (const float*)d_in[14];
    const float* ln1w   = (const float*)d_in[15];
    const float* ln2w   = (const float*)d_in[16];

    float* out   = (float*)d_out;
    float* out_k = out + HID;
    float* out_v = out_k + (size_t)HKV * SEQ * DH;
    const size_t cache_bytes = (size_t)HKV * SEQ * DH * sizeof(float);

    static cudaStream_t s2 = nullptr;
    static cudaEvent_t ev_fork = nullptr, ev_join = nullptr;
    if (!s2) {
        cudaStreamCreateWithFlags(&s2, cudaStreamNonBlocking);
        cudaEventCreateWithFlags(&ev_fork, cudaEventDisableTiming);
        cudaEventCreateWithFlags(&ev_join, cudaEventDisableTiming);
    }

    // Fork: bulk cache copy runs concurrently with the whole compute pipeline.
    cudaEventRecord(ev_fork, 0);
    cudaStreamWaitEvent(s2, ev_fork, 0);
    cudaMemcpyAsync(out_k, kcache, cache_bytes, cudaMemcpyDeviceToDevice, s2);
    cudaMemcpyAsync(out_v, vcache, cache_bytes, cudaMemcpyDeviceToDevice, s2);
    cudaEventRecord(ev_join, s2);

    gemv_qkv_k<<<(HQ*DH + 2*HKV*DH) / 8, 256>>>(x, ln1w, Wq, Wk, Wv);
    attn_k<<<HQ * NSPL, 256>>>(pos, kcache, vcache, cosv, sinv, qnw, knw);
    gemv_o_k<<<HID / 8, 256>>>(Wo, x, ln2w);
    gemv_gateup_k<<<IM / 8, 256>>>(Wg, Wu);
    gemv_down_k<<<(HID / 8) * 2, 256>>>(Wd);

    // Join: combine down halves into out and patch the copied caches.
    cudaStreamWaitEvent(0, ev_join, 0);
    finish_k<<<20, 256>>>(pos, out, out_k, out_v);
}

// round 13
// speedup vs baseline: 1.1617x; 1.0099x over previous
#include <cuda_runtime.h>
#include <math.h>
#include <stdint.h>

#define HQ   32
#define HKV  8
#define DH   128
#define HID  4096
#define IM   12288
#define SEQ  8192
#define EPSR 1e-6f
#define NSPL 16           // KV splits per head for flash decoding
#define DSPL 3            // down-proj K splits

// ---------------- scratch (device globals; no allocation allowed) ----------
__device__ __align__(16) float g_qkv[HQ*DH + 2*HKV*DH];  // q | k | v raw projections
__device__ __align__(16) float g_knew[HKV*DH];           // new K row (post rope)
__device__ __align__(16) float g_vnew[HKV*DH];           // new V row
__device__ __align__(16) float g_attn[HQ*DH];            // attention output
__device__ __align__(16) float g_h1[HID];                // residual + o_proj
__device__ __align__(16) float g_h1w[HID];               // h1 * ln2w (pre-scaled)
__device__ __align__(16) float g_m[IM];                  // silu(gate)*up
__device__ __align__(16) float g_dpart[DSPL][HID];       // down-proj split-K partials
__device__ float g_ssq;                                  // sum(h1^2); zeroed by attn_k
// split-KV partials + completion counters
__device__ __align__(16) float g_pacc[HQ*NSPL*DH];
__device__ float g_pm[HQ*NSPL];
__device__ float g_pl[HQ*NSPL];
__device__ int   g_cnt[HQ];                              // zero-init; self-resetting

// ---------------- helpers --------------------------------------------------
__device__ __forceinline__ float warp_sum(float v) {
    #pragma unroll
    for (int o = 16; o; o >>= 1) v += __shfl_xor_sync(0xffffffffu, v, o);
    return v;
}

// ============ fused RMSNorm + QKV GEMV (1 row/warp) ========================
__global__ void __launch_bounds__(256, 6)
gemv_qkv_k(const float* __restrict__ x, const float* __restrict__ lnw,
           const float* __restrict__ Wq, const float* __restrict__ Wk,
           const float* __restrict__ Wv) {
    __shared__ float4 sx[HID/4];
    __shared__ float red[8];
    int tid = threadIdx.x, warp = tid >> 5, lane = tid & 31;
    const float4* x4 = reinterpret_cast<const float4*>(x);
    const float4* w4 = reinterpret_cast<const float4*>(lnw);
    float ssq = 0.f;
    #pragma unroll
    for (int i = tid; i < HID/4; i += 256) {
        float4 v = __ldg(x4 + i);
        float4 w = __ldg(w4 + i);
        ssq += v.x*v.x + v.y*v.y + v.z*v.z + v.w*v.w;
        sx[i] = make_float4(v.x*w.x, v.y*w.y, v.z*w.z, v.w*w.w);
    }
    ssq = warp_sum(ssq);
    if (lane == 0) red[warp] = ssq;
    __syncthreads();

    int r = blockIdx.x * 8 + warp;
    const float* row;
    if (r < HQ*DH)                  row = Wq + (size_t)r * HID;
    else if (r < HQ*DH + HKV*DH)    row = Wk + (size_t)(r - HQ*DH) * HID;
    else                            row = Wv + (size_t)(r - HQ*DH - HKV*DH) * HID;
    const float4* wr = reinterpret_cast<const float4*>(row);
    float s = 0.f;
    #pragma unroll 8
    for (int i = lane; i < HID/4; i += 32) {
        float4 a = __ldcs(wr + i); float4 b = sx[i];
        s += a.x*b.x + a.y*b.y + a.z*b.z + a.w*b.w;
    }
    s = warp_sum(s);
    if (lane == 0) {
        float tot = red[0]+red[1]+red[2]+red[3]+red[4]+red[5]+red[6]+red[7];
        g_qkv[r] = s * rsqrtf(tot / (float)HID + EPSR);
    }
}

// ============ attention: fused rope + split-KV partials + last-block merge =
__global__ void attn_k(const float* __restrict__ posp,
                       const float* __restrict__ Kc, const float* __restrict__ Vc,
                       const float* __restrict__ cosv, const float* __restrict__ sinv,
                       const float* __restrict__ qw, const float* __restrict__ kw) {
    const float scale = 0.088388347648318447f;  // 128^-0.5
    int qh = blockIdx.x / NSPL;
    int sp = blockIdx.x % NSPL;
    int kv = qh >> 2;
    int tid = threadIdx.x;
    int warp = tid >> 5, lane = tid & 31;

    if (blockIdx.x == 0 && tid == 0) g_ssq = 0.f;   // reset for gemv_o epilogue

    __shared__ __align__(16) float sq[DH], sk[DH], sv[DH];
    __shared__ float redq[4], redk[4];

    // ---- prologue: per-head RMSNorm + RoPE (threads 0-127: q, 128-255: k/v)
    int t = tid & 127;
    bool doq = tid < 128;
    float v = doq ? g_qkv[qh*DH + t] : g_qkv[HQ*DH + kv*DH + t];
    float ss = warp_sum(v * v);
    if (lane == 0) { if (doq) redq[warp] = ss; else redk[warp - 4] = ss; }
    if (!doq) sv[t] = g_qkv[HQ*DH + HKV*DH + kv*DH + t];
    __syncthreads();
    float tot = doq ? (redq[0]+redq[1]+redq[2]+redq[3])
                    : (redk[0]+redk[1]+redk[2]+redk[3]);
    float inv = rsqrtf(tot / (float)DH + EPSR);
    float nv = v * inv * (doq ? qw[t] : kw[t]);
    if (doq) sq[t] = nv; else sk[t] = nv;
    __syncthreads();
    float partner;
    if (doq) partner = (t < DH/2) ? -sq[t + DH/2] : sq[t - DH/2];
    else     partner = (t < DH/2) ? -sk[t + DH/2] : sk[t - DH/2];
    float roped = nv * cosv[t] + partner * sinv[t];
    __syncthreads();
    if (doq) sq[t] = roped; else sk[t] = roped;
    __syncthreads();
    if (sp == 0 && (qh & 3) == 0 && !doq) {
        g_knew[kv*DH + t] = roped;
        g_vnew[kv*DH + t] = sv[t];
    }

    // ---- split-KV mainloop (batched 4 keys per warp iteration)
    int p = (int)posp[0];
    int total = p + 1;
    int chunk = (total + NSPL - 1) / NSPL;
    int beg = sp * chunk;
    int end = min(beg + chunk, total);
    const float* K = Kc + (size_t)kv * SEQ * DH;
    const float* V = Vc + (size_t)kv * SEQ * DH;
    float4 q = reinterpret_cast<const float4*>(sq)[lane];

    float m = -INFINITY, l = 0.f;
    float4 acc = make_float4(0.f, 0.f, 0.f, 0.f);
    for (int base = beg; base < end; base += 32) {
        float4 kx[4], vx[4];
        bool val[4];
        #pragma unroll
        for (int tt = 0; tt < 4; tt++) {
            int j = base + warp + 8*tt;
            val[tt] = (j < end);
            int jj = val[tt] ? j : beg;
            if (jj == p) {
                kx[tt] = reinterpret_cast<const float4*>(sk)[lane];
                vx[tt] = reinterpret_cast<const float4*>(sv)[lane];
            } else {
                kx[tt] = __ldg(reinterpret_cast<const float4*>(K + (size_t)jj * DH) + lane);
                vx[tt] = __ldg(reinterpret_cast<const float4*>(V + (size_t)jj * DH) + lane);
            }
        }
        float d[4];
        #pragma unroll
        for (int tt = 0; tt < 4; tt++)
            d[tt] = q.x*kx[tt].x + q.y*kx[tt].y + q.z*kx[tt].z + q.w*kx[tt].w;
        #pragma unroll
        for (int o = 16; o; o >>= 1) {
            #pragma unroll
            for (int tt = 0; tt < 4; tt++) d[tt] += __shfl_xor_sync(0xffffffffu, d[tt], o);
        }
        #pragma unroll
        for (int tt = 0; tt < 4; tt++) d[tt] = val[tt] ? d[tt] * scale : -INFINITY;
        float mb = fmaxf(fmaxf(d[0], d[1]), fmaxf(d[2], d[3]));
        if (mb > -INFINITY) {
            float mn = fmaxf(m, mb);
            float corr = (m > -INFINITY) ? __expf(m - mn) : 0.f;
            l *= corr;
            acc.x *= corr; acc.y *= corr; acc.z *= corr; acc.w *= corr;
            #pragma unroll
            for (int tt = 0; tt < 4; tt++) {
                if (val[tt]) {
                    float w = __expf(d[tt] - mn);
                    l += w;
                    acc.x += w * vx[tt].x; acc.y += w * vx[tt].y;
                    acc.z += w * vx[tt].z; acc.w += w * vx[tt].w;
                }
            }
            m = mn;
        }
    }

    // ---- block-level merge of 8 warps -> one partial
    __shared__ float s_m[8], s_l[8];
    __shared__ float s_acc[8][DH];
    if (lane == 0) { s_m[warp] = m; s_l[warp] = l; }
    s_acc[warp][4*lane + 0] = acc.x;
    s_acc[warp][4*lane + 1] = acc.y;
    s_acc[warp][4*lane + 2] = acc.z;
    s_acc[warp][4*lane + 3] = acc.w;
    __syncthreads();
    if (tid < DH) {
        int d = tid;
        float M = -INFINITY;
        #pragma unroll
        for (int w = 0; w < 8; w++) M = fmaxf(M, s_m[w]);
        float L = 0.f, A = 0.f;
        #pragma unroll
        for (int w = 0; w < 8; w++) {
            float f = (s_m[w] > -INFINITY) ? __expf(s_m[w] - M) : 0.f;
            L += s_l[w] * f;
            A += s_acc[w][d] * f;
        }
        g_pacc[(size_t)blockIdx.x * DH + d] = A;
        if (d == 0) { g_pm[blockIdx.x] = M; g_pl[blockIdx.x] = L; }
    }

    // ---- last block for this head merges all splits
    __shared__ int s_merge;
    __threadfence();
    __syncthreads();
    if (tid == 0) {
        int old = atomicAdd(&g_cnt[qh], 1);
        s_merge = (old == NSPL - 1);
        if (s_merge) g_cnt[qh] = 0;      // reset for next graph replay
    }
    __syncthreads();
    if (s_merge) {
        __threadfence();
        if (tid < DH) {
            int d = tid;
            float M = -INFINITY;
            #pragma unroll
            for (int s = 0; s < NSPL; s++) M = fmaxf(M, g_pm[qh*NSPL + s]);
            float L = 0.f, A = 0.f;
            #pragma unroll
            for (int s = 0; s < NSPL; s++) {
                float pm = g_pm[qh*NSPL + s];
                float f = (pm > -INFINITY) ? __expf(pm - M) : 0.f;
                L += g_pl[qh*NSPL + s] * f;
                A += g_pacc[(size_t)(qh*NSPL + s) * DH + d] * f;
            }
            g_attn[qh*DH + d] = A / L;
        }
    }
}

// ---------------- O projection + residual + ln2 pre-scale ------------------
__global__ void __launch_bounds__(256, 6)
gemv_o_k(const float* __restrict__ Wo, const float* __restrict__ resid,
         const float* __restrict__ ln2w) {
    __shared__ float4 sx[(HQ*DH)/4];
    __shared__ float sh1[8];
    int tid = threadIdx.x, warp = tid >> 5, lane = tid & 31;
    const float4* a4 = reinterpret_cast<const float4*>(g_attn);
    #pragma unroll
    for (int i = tid; i < (HQ*DH)/4; i += 256) sx[i] = a4[i];
    __syncthreads();
    int r = blockIdx.x * 8 + warp;
    const float4* w4 = reinterpret_cast<const float4*>(Wo + (size_t)r * (HQ*DH));
    float s = 0.f;
    #pragma unroll 8
    for (int i = lane; i < (HQ*DH)/4; i += 32) {
        float4 a = __ldcs(w4 + i); float4 b = sx[i];
        s += a.x*b.x + a.y*b.y + a.z*b.z + a.w*b.w;
    }
    s = warp_sum(s);
    if (lane == 0) {
        float h1 = resid[r] + s;
        g_h1[r] = h1;
        g_h1w[r] = h1 * ln2w[r];
        sh1[warp] = h1 * h1;
    }
    __syncthreads();
    if (tid == 0) {
        float t = sh1[0]+sh1[1]+sh1[2]+sh1[3]+sh1[4]+sh1[5]+sh1[6]+sh1[7];
        atomicAdd(&g_ssq, t);
    }
}

// ============ gate/up GEMV: pre-scaled input, scalar inv from g_ssq ========
__global__ void __launch_bounds__(256, 6)
gemv_gateup_k(const float* __restrict__ Wg, const float* __restrict__ Wu) {
    __shared__ float4 sx[HID/4];
    int tid = threadIdx.x, warp = tid >> 5, lane = tid & 31;
    const float4* x4 = reinterpret_cast<const float4*>(g_h1w);
    #pragma unroll
    for (int i = tid; i < HID/4; i += 256) sx[i] = x4[i];
    __syncthreads();

    int r = blockIdx.x * 8 + warp;
    const float4* g4 = reinterpret_cast<const float4*>(Wg + (size_t)r * HID);
    const float4* u4 = reinterpret_cast<const float4*>(Wu + (size_t)r * HID);
    float sg = 0.f, su = 0.f;
    #pragma unroll 8
    for (int i = lane; i < HID/4; i += 32) {
        float4 b = sx[i];
        float4 a = __ldcs(g4 + i);
        float4 c = __ldcs(u4 + i);
        sg += a.x*b.x + a.y*b.y + a.z*b.z + a.w*b.w;
        su += c.x*b.x + c.y*b.y + c.z*b.z + c.w*b.w;
    }
    sg = warp_sum(sg);
    su = warp_sum(su);
    if (lane == 0) {
        float inv = rsqrtf(g_ssq / (float)HID + EPSR);
        sg *= inv; su *= inv;
        g_m[r] = (sg / (1.f + __expf(-sg))) * su;
    }
}

// ---------------- down GEMV, split-K by 3 (16KB smem, 1536 blocks) ---------
// Block b: rows (b/DSPL)*8 + warp, K-third = b%DSPL. Partial into g_dpart.
__global__ void __launch_bounds__(256, 6)
gemv_down_k(const float* __restrict__ Wd) {
    __shared__ float4 sx[IM/(4*DSPL)];   // 16 KB: one third of g_m
    int tid = threadIdx.x, warp = tid >> 5, lane = tid & 31;
    int part = blockIdx.x % DSPL;
    int base4 = part * (IM/(4*DSPL));    // offset in float4 units
    const float4* m4 = reinterpret_cast<const float4*>(g_m) + base4;
    #pragma unroll
    for (int i = tid; i < IM/(4*DSPL); i += 256) sx[i] = m4[i];
    __syncthreads();
    int r = (blockIdx.x / DSPL) * 8 + warp;
    const float4* w4 = reinterpret_cast<const float4*>(Wd + (size_t)r * IM) + base4;
    float s = 0.f;
    #pragma unroll 8
    for (int i = lane; i < IM/(4*DSPL); i += 32) {
        float4 a = __ldcs(w4 + i); float4 b = sx[i];
        s += a.x*b.x + a.y*b.y + a.z*b.z + a.w*b.w;
    }
    s = warp_sum(s);
    if (lane == 0) g_dpart[part][r] = s;
}

// ---------------- finish: combine down thirds + patch cache row ------------
// grid = 20 x 256: blocks 0-15 -> out combine (4096), blocks 16-19 -> patch.
__global__ void finish_k(const float* __restrict__ posp,
                         float* __restrict__ out,
                         float* __restrict__ out_k, float* __restrict__ out_v) {
    int gi = blockIdx.x * 256 + threadIdx.x;
    if (blockIdx.x < 16) {
        out[gi] = g_h1[gi] + g_dpart[0][gi] + g_dpart[1][gi] + g_dpart[2][gi];
    } else {
        int i = gi - 16*256;             // 0..1023 = HKV*DH
        int head = i >> 7, t = i & 127;
        int p = (int)posp[0];
        size_t off = (size_t)head * SEQ * DH + (size_t)p * DH + t;
        out_k[off] = g_knew[i];
        out_v[off] = g_vnew[i];
    }
}

// ---------------- launch ----------------------------------------------------
extern "C" void kernel_launch(void* const* d_in, const int* in_sizes, int n_in,
                              void* d_out, int out_size) {
    const float* x      = (const float*)d_in[0];
    const float* pos    = (const float*)d_in[1];
    const float* cosv   = (const float*)d_in[2];
    const float* sinv   = (const float*)d_in[3];
    const float* kcache = (const float*)d_in[4];
    const float* vcache = (const float*)d_in[5];
    const float* Wq     = (const float*)d_in[6];
    const float* Wk     = (const float*)d_in[7];
    const float* Wv     = (const float*)d_in[8];
    const float* Wo     = (const float*)d_in[9];
    const float* Wg     = (const float*)d_in[10];
    const float* Wu     = (const float*)d_in[11];
    const float* Wd     = (const float*)d_in[12];
    const float* qnw    = (const float*)d_in[13];
    const float* knw    = (const float*)d_in[14];
    const float* ln1w   = (const float*)d_in[15];
    const float* ln2w   = (const float*)d_in[16];

    float* out   = (float*)d_out;
    float* out_k = out + HID;
    float* out_v = out_k + (size_t)HKV * SEQ * DH;
    const size_t cache_bytes = (size_t)HKV * SEQ * DH * sizeof(float);

    static cudaStream_t s2 = nullptr;
    static cudaEvent_t ev_fork = nullptr, ev_join = nullptr;
    if (!s2) {
        cudaStreamCreateWithFlags(&s2, cudaStreamNonBlocking);
        cudaEventCreateWithFlags(&ev_fork, cudaEventDisableTiming);
        cudaEventCreateWithFlags(&ev_join, cudaEventDisableTiming);
    }

    // Fork: bulk cache copy runs concurrently with the whole compute pipeline.
    cudaEventRecord(ev_fork, 0);
    cudaStreamWaitEvent(s2, ev_fork, 0);
    cudaMemcpyAsync(out_k, kcache, cache_bytes, cudaMemcpyDeviceToDevice, s2);
    cudaMemcpyAsync(out_v, vcache, cache_bytes, cudaMemcpyDeviceToDevice, s2);
    cudaEventRecord(ev_join, s2);

    gemv_qkv_k<<<(HQ*DH + 2*HKV*DH) / 8, 256>>>(x, ln1w, Wq, Wk, Wv);
    attn_k<<<HQ * NSPL, 256>>>(pos, kcache, vcache, cosv, sinv, qnw, knw);
    gemv_o_k<<<HID / 8, 256>>>(Wo, x, ln2w);
    gemv_gateup_k<<<IM / 8, 256>>>(Wg, Wu);
    gemv_down_k<<<(HID / 8) * DSPL, 256>>>(Wd);

    // Join: combine down thirds into out and patch the copied caches.
    cudaStreamWaitEvent(0, ev_join, 0);
    finish_k<<<20, 256>>>(pos, out, out_k, out_v);
}